// round 10
// baseline (speedup 1.0000x reference)
#include <cuda_runtime.h>
#include <cuda_bf16.h>
#include <mma.h>
#include <math.h>
#include <stdint.h>

using namespace nvcuda;

#define Bdim 128
#define Tdim 512
#define Idim 300
#define Hdim 256
#define G4H  1024   // 4*H gate rows
#define NSTEP 512

#define KBLK 5      // K padded 300 -> 320 = 5 blocks of 64 bf16
#define GPITCH 72   // smem pitch (bf16 elems) for gemm_wmma tiles

// ---------------------------------------------------------------------------
// Scratch (static __device__ globals; no allocation anywhere)
// ---------------------------------------------------------------------------
__device__ float g_xp[(size_t)Bdim * Tdim * G4H];   // 256 MB: x @ W_ih_f^T (no bias)
__device__ float g_xpb[Bdim * G4H];                 // backward projection at t=T-1
__device__ float g_h[2][Bdim][Hdim];                // final hidden state (parity 0 used)
__device__ unsigned int g_bar[16];                  // (legacy, zeroed, unused)

// packed bf16 hi/lo operand tiles, plain linear layout:
__device__ uint4 g_Ah[(size_t)512 * KBLK * 1024];
__device__ uint4 g_Al[(size_t)512 * KBLK * 1024];
__device__ uint4 g_Bh[8 * KBLK * 1024];
__device__ uint4 g_Bl[8 * KBLK * 1024];

// ---------------------------------------------------------------------------
__device__ __forceinline__ uint32_t smem_u32(const void* p) {
    uint32_t a;
    asm("{ .reg .u64 t; cvta.to.shared.u64 t, %1; cvt.u32.u64 %0, t; }"
        : "=r"(a) : "l"(p));
    return a;
}
__device__ __forceinline__ void st_cluster_b16(uint32_t laddr, uint32_t rank,
                                               uint16_t v) {
    uint32_t ra;
    asm volatile("mapa.shared::cluster.u32 %0, %1, %2;"
                 : "=r"(ra) : "r"(laddr), "r"(rank));
    asm volatile("st.shared::cluster.b16 [%0], %1;" :: "r"(ra), "h"(v) : "memory");
}

// ---------------------------------------------------------------------------
__global__ void init_k()
{
    int i = blockIdx.x * blockDim.x + threadIdx.x;
    if (i < Bdim * Hdim) ((float*)g_h)[i] = 0.f;
    if (i < 16) g_bar[i] = 0u;
}

// ---------------------------------------------------------------------------
// conv_pack: fp32 rows [rows x Idim] -> bf16 hi/lo packed tiles (linear).
// ---------------------------------------------------------------------------
__global__ void conv_pack(const float* __restrict__ src, int rows,
                          uint4* __restrict__ Hc, uint4* __restrict__ Lc)
{
    int id = blockIdx.x * blockDim.x + threadIdx.x;
    int total = rows * 40;
    if (id >= total) return;
    int m  = id / 40;
    int g  = id % 40;
    int k0 = g * 8;

    union U8 { uint4 u; __nv_bfloat16 b[8]; } hu, lu;
#pragma unroll
    for (int j = 0; j < 8; j++) {
        int k = k0 + j;
        float v = (k < Idim) ? src[(size_t)m * Idim + k] : 0.f;
        __nv_bfloat16 h = __float2bfloat16(v);
        hu.b[j] = h;
        lu.b[j] = __float2bfloat16(v - __bfloat162float(h));
    }

    int tile = m >> 7;
    int r    = m & 127;
    int blk  = k0 >> 6;
    int c8   = (k0 & 63) >> 3;
    size_t idx = ((size_t)tile * KBLK + blk) * 1024 + (size_t)r * 8 + c8;
    Hc[idx] = hu.u;
    Lc[idx] = lu.u;
}

// ---------------------------------------------------------------------------
// gemm_wmma (unchanged from R6 passing kernel): xp = x @ W_ih_f^T, split-bf16
// ---------------------------------------------------------------------------
#define GEMM_SMEM (4 * 128 * GPITCH * 2)

__global__ void __launch_bounds__(256) gemm_wmma(
    const uint4* __restrict__ Ah, const uint4* __restrict__ Al,
    const uint4* __restrict__ Bh, const uint4* __restrict__ Bl,
    float* __restrict__ C)
{
    extern __shared__ __nv_bfloat16 sm[];
    __nv_bfloat16* sAh = sm;
    __nv_bfloat16* sAl = sm + 128 * GPITCH;
    __nv_bfloat16* sBh = sm + 2 * 128 * GPITCH;
    __nv_bfloat16* sBl = sm + 3 * 128 * GPITCH;

    int tid = threadIdx.x;
    int wid = tid >> 5;
    int wm  = wid >> 2;
    int wn  = wid & 3;
    int nt  = blockIdx.x;
    int mt  = blockIdx.y;

    wmma::fragment<wmma::accumulator, 16, 16, 16, float> acc[4][2];
#pragma unroll
    for (int i = 0; i < 4; i++)
#pragma unroll
        for (int j = 0; j < 2; j++) wmma::fill_fragment(acc[i][j], 0.f);

    for (int blk = 0; blk < KBLK; blk++) {
        const uint4* gA_h = Ah + ((size_t)mt * KBLK + blk) * 1024;
        const uint4* gA_l = Al + ((size_t)mt * KBLK + blk) * 1024;
        const uint4* gB_h = Bh + ((size_t)nt * KBLK + blk) * 1024;
        const uint4* gB_l = Bl + ((size_t)nt * KBLK + blk) * 1024;
        uint4* dAh = (uint4*)sAh;
        uint4* dAl = (uint4*)sAl;
        uint4* dBh = (uint4*)sBh;
        uint4* dBl = (uint4*)sBl;
#pragma unroll
        for (int it = 0; it < 4; it++) {
            int i = it * 256 + tid;
            int r = i >> 3, c = i & 7;
            int d = r * 9 + c;
            dAh[d] = gA_h[i];
            dAl[d] = gA_l[i];
            dBh[d] = gB_h[i];
            dBl[d] = gB_l[i];
        }
        __syncthreads();

#pragma unroll
        for (int prod = 0; prod < 3; prod++) {
            const __nv_bfloat16* As = (prod == 2) ? sAl : sAh;
            const __nv_bfloat16* Bs = (prod == 1) ? sBl : sBh;
#pragma unroll
            for (int ks = 0; ks < 4; ks++) {
                wmma::fragment<wmma::matrix_a, 16, 16, 16, __nv_bfloat16,
                               wmma::row_major> af[4];
                wmma::fragment<wmma::matrix_b, 16, 16, 16, __nv_bfloat16,
                               wmma::col_major> bfr[2];
#pragma unroll
                for (int i = 0; i < 4; i++)
                    wmma::load_matrix_sync(
                        af[i], As + (wm * 64 + i * 16) * GPITCH + ks * 16, GPITCH);
#pragma unroll
                for (int j = 0; j < 2; j++)
                    wmma::load_matrix_sync(
                        bfr[j], Bs + (wn * 32 + j * 16) * GPITCH + ks * 16, GPITCH);
#pragma unroll
                for (int i = 0; i < 4; i++)
#pragma unroll
                    for (int j = 0; j < 2; j++)
                        wmma::mma_sync(acc[i][j], af[i], bfr[j], acc[i][j]);
            }
        }
        __syncthreads();
    }

    size_t row0 = (size_t)mt * 128 + wm * 64;
    int    col0 = nt * 128 + wn * 32;
#pragma unroll
    for (int i = 0; i < 4; i++)
#pragma unroll
        for (int j = 0; j < 2; j++)
            wmma::store_matrix_sync(
                C + (row0 + i * 16) * G4H + col0 + j * 16,
                acc[i][j], G4H, wmma::mem_row_major);
}

// ---------------------------------------------------------------------------
// fp32 SGEMM (tiny backward projection at t = T-1; includes bias)
// ---------------------------------------------------------------------------
__global__ void __launch_bounds__(256) sgemm_bias(
    const float* __restrict__ A, long lda,
    const float* __restrict__ W,
    const float* __restrict__ bias,
    float* __restrict__ C)
{
    __shared__ float As[8][128];
    __shared__ float Bs[8][128];
    int tid  = threadIdx.x;
    long row0 = (long)blockIdx.y * 128;
    int  col0 = blockIdx.x * 128;
    int  lm = tid >> 1;
    int  lk = (tid & 1) * 4;
    int  tx = tid & 15, ty = tid >> 4;

    float bsv[8];
    *(float4*)(bsv)     = *(const float4*)&bias[col0 + tx * 8];
    *(float4*)(bsv + 4) = *(const float4*)&bias[col0 + tx * 8 + 4];

    float acc[8][8];
#pragma unroll
    for (int i = 0; i < 8; i++)
#pragma unroll
        for (int j = 0; j < 8; j++) acc[i][j] = 0.f;

    for (int k0 = 0; k0 < Idim; k0 += 8) {
        float4 av = make_float4(0.f, 0.f, 0.f, 0.f);
        float4 bv = make_float4(0.f, 0.f, 0.f, 0.f);
        if (k0 + lk < Idim) {
            av = *(const float4*)(A + (row0 + lm) * lda + k0 + lk);
            bv = *(const float4*)(W + (long)(col0 + lm) * Idim + k0 + lk);
        }
        __syncthreads();
        As[lk + 0][lm] = av.x; As[lk + 1][lm] = av.y;
        As[lk + 2][lm] = av.z; As[lk + 3][lm] = av.w;
        Bs[lk + 0][lm] = bv.x; Bs[lk + 1][lm] = bv.y;
        Bs[lk + 2][lm] = bv.z; Bs[lk + 3][lm] = bv.w;
        __syncthreads();
#pragma unroll
        for (int k = 0; k < 8; k++) {
            float a[8], b[8];
            *(float4*)(a)     = *(const float4*)&As[k][ty * 8];
            *(float4*)(a + 4) = *(const float4*)&As[k][ty * 8 + 4];
            *(float4*)(b)     = *(const float4*)&Bs[k][tx * 8];
            *(float4*)(b + 4) = *(const float4*)&Bs[k][tx * 8 + 4];
#pragma unroll
            for (int i = 0; i < 8; i++)
#pragma unroll
                for (int j = 0; j < 8; j++)
                    acc[i][j] = fmaf(a[i], b[j], acc[i][j]);
        }
    }

#pragma unroll
    for (int i = 0; i < 8; i++) {
        long r = row0 + ty * 8 + i;
        float4 o0 = make_float4(acc[i][0] + bsv[0], acc[i][1] + bsv[1],
                                acc[i][2] + bsv[2], acc[i][3] + bsv[3]);
        float4 o1 = make_float4(acc[i][4] + bsv[4], acc[i][5] + bsv[5],
                                acc[i][6] + bsv[6], acc[i][7] + bsv[7]);
        *(float4*)&C[r * G4H + col0 + tx * 8]     = o0;
        *(float4*)&C[r * G4H + col0 + tx * 8 + 4] = o1;
    }
}

// ---------------------------------------------------------------------------
// lstm_fwd_tc: persistent HMMA recurrence with cluster DSMEM h-exchange.
// 16 clusters (batch groups of 8) x 8 CTAs (32 H-cols each), 256 thr/CTA.
// Per step:  A = h-tile (16x256 bf16 hi/lo, rows 8-15 zero), B = resident
// W tile (128x256 bf16 hi/lo).  Warps 0-3: n=32 each, K=256, 3 split
// products -> sacc.  All threads: gates + c update; new h bf16 hi/lo stored
// into all 8 cluster CTAs' A-buffers (parity-flipped) via st.shared::cluster;
// one barrier.cluster per step.
// ---------------------------------------------------------------------------
#define WP     264                 // bf16 pitch: 528B rows, ldsm conflict-free
#define SACC_P 136
#define OFF_WLO  67584             // 128*WP*2
#define OFF_HHI  135168            // [2][16][WP] bf16, parity stride 8448 B
#define OFF_HLO  152064
#define OFF_SACC 168960            // fp32 [16][136]
#define TC_SMEM  177664

__device__ __forceinline__ float sigf(float x) { return 1.f / (1.f + __expf(-x)); }

__global__ void __launch_bounds__(256, 1) __cluster_dims__(8, 1, 1)
lstm_fwd_tc(const float* __restrict__ Whh, const float* __restrict__ bias)
{
    extern __shared__ char smraw[];
    __nv_bfloat16* Whi = (__nv_bfloat16*)smraw;
    __nv_bfloat16* Wlo = (__nv_bfloat16*)(smraw + OFF_WLO);
    __nv_bfloat16* Hhi = (__nv_bfloat16*)(smraw + OFF_HHI);
    __nv_bfloat16* Hlo = (__nv_bfloat16*)(smraw + OFF_HLO);
    float*         sac = (float*)(smraw + OFF_SACC);

    int tid = threadIdx.x;
    int wid = tid >> 5;
    int gb  = blockIdx.x >> 3;               // batch group 0..15
    int gj  = blockIdx.x & 7;                // cluster rank = col group
    int b0  = gb * 8;
    int j0  = gj * 32;

    // one-time: W tile -> smem bf16 hi/lo.  local row lr = gate*32 + jj
    for (int idx = tid; idx < 128 * 256; idx += 256) {
        int lr = idx >> 8, k = idx & 255;
        int grow = ((lr >> 5) << 8) + j0 + (lr & 31);
        float v = Whh[grow * Hdim + k];
        __nv_bfloat16 h = __float2bfloat16(v);
        Whi[lr * WP + k] = h;
        Wlo[lr * WP + k] = __float2bfloat16(v - __bfloat162float(h));
    }
    // zero both parities of the h operand buffers (incl. pad rows 8-15)
    {
        __nv_bfloat16 z = __float2bfloat16(0.f);
        for (int idx = tid; idx < 2 * 16 * WP; idx += 256) {
            Hhi[idx] = z;
            Hlo[idx] = z;
        }
    }

    int bred = tid >> 5;                     // batch within group (0..7)
    int jj   = tid & 31;                     // H-col within group
    float bgate[4];
#pragma unroll
    for (int g = 0; g < 4; g++) bgate[g] = bias[g * 256 + j0 + jj];
    float c = 0.f;

    uint32_t hhi_base = smem_u32(Hhi);
    uint32_t hlo_base = smem_u32(Hlo);

    __syncthreads();
    asm volatile("barrier.cluster.arrive.aligned;" ::: "memory");
    asm volatile("barrier.cluster.wait.aligned;"  ::: "memory");

    for (int t = 0; t < NSTEP; t++) {
        // xp prefetch (consumed ~2k cyc later)
        float xg[4];
        {
            size_t base = ((size_t)(b0 + bred) * Tdim + t) * G4H + j0 + jj;
#pragma unroll
            for (int g = 0; g < 4; g++) xg[g] = g_xp[base + (size_t)g * 256];
        }

        int p = t & 1;
        const __nv_bfloat16* Ahp = Hhi + p * 16 * WP;
        const __nv_bfloat16* Alp = Hlo + p * 16 * WP;

        if (wid < 4) {
            wmma::fragment<wmma::accumulator, 16, 16, 16, float> ac0, ac1;
            wmma::fill_fragment(ac0, 0.f);
            wmma::fill_fragment(ac1, 0.f);
            const __nv_bfloat16* Bh0 = Whi + (wid * 32) * WP;
            const __nv_bfloat16* Bh1 = Bh0 + 16 * WP;
            const __nv_bfloat16* Bl0 = Wlo + (wid * 32) * WP;
            const __nv_bfloat16* Bl1 = Bl0 + 16 * WP;
#pragma unroll
            for (int k0 = 0; k0 < 256; k0 += 16) {
                wmma::fragment<wmma::matrix_a, 16, 16, 16, __nv_bfloat16,
                               wmma::row_major> ah, al;
                wmma::fragment<wmma::matrix_b, 16, 16, 16, __nv_bfloat16,
                               wmma::col_major> bh0, bh1, bl0, bl1;
                wmma::load_matrix_sync(ah, Ahp + k0, WP);
                wmma::load_matrix_sync(al, Alp + k0, WP);
                wmma::load_matrix_sync(bh0, Bh0 + k0, WP);
                wmma::load_matrix_sync(bh1, Bh1 + k0, WP);
                wmma::load_matrix_sync(bl0, Bl0 + k0, WP);
                wmma::load_matrix_sync(bl1, Bl1 + k0, WP);
                wmma::mma_sync(ac0, ah, bh0, ac0);
                wmma::mma_sync(ac1, ah, bh1, ac1);
                wmma::mma_sync(ac0, ah, bl0, ac0);
                wmma::mma_sync(ac1, ah, bl1, ac1);
                wmma::mma_sync(ac0, al, bh0, ac0);
                wmma::mma_sync(ac1, al, bh1, ac1);
            }
            wmma::store_matrix_sync(sac + wid * 32,      ac0, SACC_P,
                                    wmma::mem_row_major);
            wmma::store_matrix_sync(sac + wid * 32 + 16, ac1, SACC_P,
                                    wmma::mem_row_major);
        }
        __syncthreads();

        // gates + state update; thread owns (b0+bred, j0+jj)
        float gsum[4];
#pragma unroll
        for (int g = 0; g < 4; g++)
            gsum[g] = sac[bred * SACC_P + g * 32 + jj] + xg[g] + bgate[g];
        float ig = sigf(gsum[0]);
        float fg = sigf(gsum[1]);
        float gg = tanhf(gsum[2]);
        float og = sigf(gsum[3]);
        c = fg * c + ig * gg;
        float h = og * tanhf(c);

        if (t == NSTEP - 1) {
            g_h[0][b0 + bred][j0 + jj] = h;
        } else {
            __nv_bfloat16 hh = __float2bfloat16(h);
            __nv_bfloat16 hl = __float2bfloat16(h - __bfloat162float(hh));
            uint16_t hu = __bfloat16_as_ushort(hh);
            uint16_t lu = __bfloat16_as_ushort(hl);
            uint32_t off = (uint32_t)(((p ^ 1) * 16 + bred) * WP + j0 + jj) * 2;
            uint32_t ahi = hhi_base + off;
            uint32_t alo = hlo_base + off;
#pragma unroll
            for (uint32_t r = 0; r < 8; r++) {
                st_cluster_b16(ahi, r, hu);
                st_cluster_b16(alo, r, lu);
            }
            asm volatile("barrier.cluster.arrive.aligned;" ::: "memory");
            asm volatile("barrier.cluster.wait.aligned;"  ::: "memory");
        }
    }
}

// ---------------------------------------------------------------------------
// Final: hb_last = ONE backward step from zero state on x[:,T-1]
// ---------------------------------------------------------------------------
__global__ void final_k(const float* __restrict__ Wlin,
                        const float* __restrict__ blin,
                        float* __restrict__ out)
{
    int b = threadIdx.x;
    float a0 = blin[0], a1 = blin[1];
    const float* hf = &g_h[0][b][0];
#pragma unroll 4
    for (int j = 0; j < Hdim; j++) {
        float h = hf[j];
        a0 = fmaf(h, Wlin[j], a0);
        a1 = fmaf(h, Wlin[512 + j], a1);
    }
    const float* xb = &g_xpb[b * G4H];
#pragma unroll 4
    for (int j = 0; j < Hdim; j++) {
        float ig = 1.f / (1.f + __expf(-xb[j]));
        float gg = tanhf(xb[512 + j]);
        float og = 1.f / (1.f + __expf(-xb[768 + j]));
        float cc = ig * gg;
        float h  = og * tanhf(cc);
        a0 = fmaf(h, Wlin[256 + j], a0);
        a1 = fmaf(h, Wlin[768 + j], a1);
    }
    out[b * 2]     = a0;
    out[b * 2 + 1] = a1;
}

// ---------------------------------------------------------------------------
// launch
// ---------------------------------------------------------------------------
extern "C" void kernel_launch(void* const* d_in, const int* in_sizes, int n_in,
                              void* d_out, int out_size)
{
    const float* x    = (const float*)d_in[0];
    const float* Wihf = (const float*)d_in[1];
    const float* Whhf = (const float*)d_in[2];
    const float* bf   = (const float*)d_in[3];
    const float* Wihb = (const float*)d_in[4];
    // d_in[5] = W_hh_b: unused (backward output only needs its first step)
    const float* bb   = (const float*)d_in[6];
    const float* Wlin = (const float*)d_in[7];
    const float* blin = (const float*)d_in[8];
    float* out = (float*)d_out;

    void *xp_ptr = nullptr, *xpb_ptr = nullptr;
    void *ah = nullptr, *al = nullptr, *bh = nullptr, *bl = nullptr;
    cudaGetSymbolAddress(&xp_ptr,  g_xp);
    cudaGetSymbolAddress(&xpb_ptr, g_xpb);
    cudaGetSymbolAddress(&ah, g_Ah);
    cudaGetSymbolAddress(&al, g_Al);
    cudaGetSymbolAddress(&bh, g_Bh);
    cudaGetSymbolAddress(&bl, g_Bl);

    cudaFuncSetAttribute(gemm_wmma, cudaFuncAttributeMaxDynamicSharedMemorySize,
                         GEMM_SMEM);
    cudaFuncSetAttribute(lstm_fwd_tc, cudaFuncAttributeMaxDynamicSharedMemorySize,
                         TC_SMEM);

    init_k<<<128, 256>>>();

    // split-bf16 operand packing (plain linear tiles)
    conv_pack<<<(65536 * 40 + 255) / 256, 256>>>(x, 65536, (uint4*)ah, (uint4*)al);
    conv_pack<<<(1024 * 40 + 255) / 256, 256>>>(Wihf, 1024, (uint4*)bh, (uint4*)bl);

    // xp_f = x @ W_ih_f^T on HMMA tensor path
    gemm_wmma<<<dim3(8, 512), 256, GEMM_SMEM>>>(
        (const uint4*)ah, (const uint4*)al, (const uint4*)bh, (const uint4*)bl,
        (float*)xp_ptr);

    // backward projection at t = T-1 only (tiny, fp32, bias included)
    sgemm_bias<<<dim3(8, 1), 256>>>(x + (long)(Tdim - 1) * Idim,
                                    (long)Tdim * Idim, Wihb, bb,
                                    (float*)xpb_ptr);

    // persistent HMMA recurrence (clusters of 8, DSMEM h-exchange)
    lstm_fwd_tc<<<128, 256, TC_SMEM>>>(Whhf, bf);

    // epilogue
    final_k<<<1, 128>>>(Wlin, blin, out);
}